// round 12
// baseline (speedup 1.0000x reference)
#include <cuda_runtime.h>
#include <cstdint>
#include <math.h>

#define BSZ 1024      // batch (edge events)
#define NND 1024      // nodes
#define DIM 256       // feature dim
#define K3  768       // 3*DIM

// GEMM tiling
#define BM 64
#define BN 64
#define BKK 32        // K per stage
#define SSTR 36       // smem row stride (floats): conflict-free + 16B aligned rows

// ---------------- scratch (device globals; no allocation) ----------------
__device__ __align__(16) float g_H0[BSZ * DIM];
__device__ __align__(16) float g_H1[BSZ * DIM];
__device__ __align__(16) float g_sums[NND * DIM];
__device__ __align__(16) float g_cnt[NND];
__device__ __align__(16) float g_GI[NND * K3];
__device__ __align__(16) float g_GH[NND * K3];

// ---------------- PTX helpers ----------------
__device__ __forceinline__ uint32_t smem_u32(const void* p) {
    uint32_t a;
    asm("{ .reg .u64 t; cvta.to.shared.u64 t, %1; cvt.u32.u64 %0, t; }" : "=r"(a) : "l"(p));
    return a;
}
__device__ __forceinline__ uint32_t f2tf32(float x) {
    uint32_t r;
    asm("cvt.rna.tf32.f32 %0, %1;" : "=r"(r) : "f"(x));
    return r;
}
#define CP16(dst, src) \
    asm volatile("cp.async.cg.shared.global [%0], [%1], 16;" :: "r"(dst), "l"(src))
#define CP_COMMIT() asm volatile("cp.async.commit_group;" ::: "memory")
#define CP_WAIT0()  asm volatile("cp.async.wait_group 0;" ::: "memory")
#define CP_WAIT1()  asm volatile("cp.async.wait_group 1;" ::: "memory")

__device__ __forceinline__ void mma_tf32(float* c, const uint32_t* a, const uint32_t* b) {
    asm volatile(
        "mma.sync.aligned.m16n8k8.row.col.f32.tf32.tf32.f32 "
        "{%0,%1,%2,%3}, {%4,%5,%6,%7}, {%8,%9}, {%0,%1,%2,%3};"
        : "+f"(c[0]), "+f"(c[1]), "+f"(c[2]), "+f"(c[3])
        : "r"(a[0]), "r"(a[1]), "r"(a[2]), "r"(a[3]), "r"(b[0]), "r"(b[1]));
}

// ---------------- counts ----------------
__global__ void count_kernel(const int* __restrict__ src,
                             const int* __restrict__ tgt) {
    int i = blockIdx.x * blockDim.x + threadIdx.x;
    if (i < BSZ) {
        atomicAdd(&g_cnt[src[i]], 1.0f);
        atomicAdd(&g_cnt[tgt[i]], 1.0f);
    }
}

// ---------------- tf32 mma.sync GEMM ----------------
// C[M,N] = A[M,K] @ W[N,K]^T + bias[N]
// mode 0: store, 1: relu+store, 2: atomicAdd into g_sums[sidx[row]*DIM + col]
// divA:   scale output row r by 1/max(g_cnt[bm+r],1) (fused agg divide, epilogue)
// gather: A row r is the virtual concat [memory[idxA[r]], memory[idxB[r]],
//         dtv[r, idxA[r]]] (no materialization; segment = k>>8)
struct GemmArgs {
    const float* A;       // plain-A base (gather=0)
    const float* W;
    const float* bias;
    float* C;
    const int* sidx;      // scatter indices (mode 2)
    int divA;
    int gather;
    const int* idxA;      // gather: seg0 + dt indices
    const int* idxB;      // gather: seg1 indices
    const float* mem;     // gather: memory base
    const float* dtv;     // gather: delta_t_vec base
};

__global__ __launch_bounds__(128) void mma_gemm_kernel(GemmArgs a0, GemmArgs a1,
                                                       int N, int K, int mode) {
    __shared__ __align__(16) float As[2][BM][SSTR];
    __shared__ __align__(16) float Bs[2][BN][SSTR];

    GemmArgs ga = (blockIdx.z == 0) ? a0 : a1;
    const float* __restrict__ W = ga.W;

    int bm = blockIdx.y * BM;
    int bn = blockIdx.x * BN;
    int tid = threadIdx.x;
    int wid = tid >> 5;
    int lane = tid & 31;
    int gidq = lane >> 2;   // group id 0..7
    int tig  = lane & 3;    // thread in group 0..3
    int wm = wid & 1;       // warp m (2)
    int wn = wid >> 1;      // warp n (2)

    float acc[2][4][4];
#pragma unroll
    for (int i = 0; i < 2; i++)
#pragma unroll
        for (int j = 0; j < 4; j++)
#pragma unroll
            for (int l = 0; l < 4; l++) acc[i][j][l] = 0.0f;

    int nst = K >> 5;   // stages of BKK=32

    // loader: per stage, 512 16B-chunks (A) + 512 (B); 128 thr x 4 each.
    // cid -> row = cid>>3 (0..63), ch = cid&7 (16B chunk within 32-float stage)
    // A source address for stage with k-base kb:
    //   gather=0: A + (bm+row)*K + kb + ch*4
    //   gather=1: segment s = kb>>8, segcol = kb&255:
    //      s==0 -> mem + idxA[bm+row]*DIM + segcol + ch*4
    //      s==1 -> mem + idxB[bm+row]*DIM + segcol + ch*4
    //      s==2 -> dtv + ((bm+row)*NND + idxA[bm+row])*DIM + segcol + ch*4
#define LOAD_STAGE(bufi, kb)                                                        \
    do {                                                                            \
        int seg = (kb) >> 8;                                                        \
        int segcol = (kb) & 255;                                                    \
        _Pragma("unroll")                                                           \
        for (int i = 0; i < 4; i++) {                                               \
            int cid = tid + i * 128;                                                \
            int row = cid >> 3;                                                     \
            int ch  = cid & 7;                                                      \
            const float* asrc;                                                      \
            if (!ga.gather) {                                                       \
                asrc = ga.A + (size_t)(bm + row) * K + (kb) + ch * 4;               \
            } else if (seg == 0) {                                                  \
                asrc = ga.mem + (size_t)__ldg(&ga.idxA[bm + row]) * DIM + segcol + ch * 4; \
            } else if (seg == 1) {                                                  \
                asrc = ga.mem + (size_t)__ldg(&ga.idxB[bm + row]) * DIM + segcol + ch * 4; \
            } else {                                                                \
                asrc = ga.dtv + ((size_t)(bm + row) * NND +                         \
                       (size_t)__ldg(&ga.idxA[bm + row])) * DIM + segcol + ch * 4;  \
            }                                                                       \
            CP16(smem_u32(&As[bufi][row][ch * 4]), asrc);                           \
            CP16(smem_u32(&Bs[bufi][row][ch * 4]),                                  \
                 W + (size_t)(bn + row) * K + (kb) + ch * 4);                       \
        }                                                                           \
        CP_COMMIT();                                                                \
    } while (0)

    LOAD_STAGE(0, 0);

    int buf = 0;
    for (int s = 0; s < nst; s++) {
        if (s + 1 < nst) {
            int nb = buf ^ 1;
            LOAD_STAGE(nb, (s + 1) * BKK);
            CP_WAIT1();
        } else {
            CP_WAIT0();
        }
        __syncthreads();

        // compute this stage: 4 k-steps of 8
#pragma unroll
        for (int ks = 0; ks < 4; ks++) {
            int k0 = ks * 8;
            uint32_t afr[2][4];
#pragma unroll
            for (int ma = 0; ma < 2; ma++) {
                int r = wm * 32 + ma * 16 + gidq;
                afr[ma][0] = f2tf32(As[buf][r][k0 + tig]);
                afr[ma][1] = f2tf32(As[buf][r + 8][k0 + tig]);
                afr[ma][2] = f2tf32(As[buf][r][k0 + tig + 4]);
                afr[ma][3] = f2tf32(As[buf][r + 8][k0 + tig + 4]);
            }
            uint32_t bfr[4][2];
#pragma unroll
            for (int na = 0; na < 4; na++) {
                int c = wn * 32 + na * 8 + gidq;
                bfr[na][0] = f2tf32(Bs[buf][c][k0 + tig]);
                bfr[na][1] = f2tf32(Bs[buf][c][k0 + tig + 4]);
            }
#pragma unroll
            for (int ma = 0; ma < 2; ma++)
#pragma unroll
                for (int na = 0; na < 4; na++)
                    mma_tf32(acc[ma][na], afr[ma], bfr[na]);
        }
        __syncthreads();
        buf ^= 1;
    }

    // ---- epilogue: bias / relu / divA-scale / scatter ----
#pragma unroll
    for (int ma = 0; ma < 2; ma++) {
        int rl0 = wm * 32 + ma * 16 + gidq;   // local rows
        int rl1 = rl0 + 8;
        float s0 = 1.0f, s1 = 1.0f;
        if (ga.divA) {
            s0 = 1.0f / fmaxf(g_cnt[bm + rl0], 1.0f);
            s1 = 1.0f / fmaxf(g_cnt[bm + rl1], 1.0f);
        }
#pragma unroll
        for (int na = 0; na < 4; na++) {
            int cl = wn * 32 + na * 8 + tig * 2;
            int cg = bn + cl;
            float b0v = ga.bias[cg];
            float b1v = ga.bias[cg + 1];
            float v00 = acc[ma][na][0] * s0 + b0v;
            float v01 = acc[ma][na][1] * s0 + b1v;
            float v10 = acc[ma][na][2] * s1 + b0v;
            float v11 = acc[ma][na][3] * s1 + b1v;
            if (mode == 1) {
                v00 = fmaxf(v00, 0.0f); v01 = fmaxf(v01, 0.0f);
                v10 = fmaxf(v10, 0.0f); v11 = fmaxf(v11, 0.0f);
            }
            if (mode == 2) {
                int n0 = ga.sidx[bm + rl0];
                int n1 = ga.sidx[bm + rl1];
                atomicAdd(&g_sums[(size_t)n0 * DIM + cg],     v00);
                atomicAdd(&g_sums[(size_t)n0 * DIM + cg + 1], v01);
                atomicAdd(&g_sums[(size_t)n1 * DIM + cg],     v10);
                atomicAdd(&g_sums[(size_t)n1 * DIM + cg + 1], v11);
            } else {
                *reinterpret_cast<float2*>(ga.C + (size_t)(bm + rl0) * N + cg) =
                    make_float2(v00, v01);
                *reinterpret_cast<float2*>(ga.C + (size_t)(bm + rl1) * N + cg) =
                    make_float2(v10, v11);
            }
        }
    }
}

// ---------------- GRU elementwise + touched mask ----------------
__global__ void gru_kernel(const float* __restrict__ memory,
                           float* __restrict__ out) {
    int gid = blockIdx.x * blockDim.x + threadIdx.x;
    int n  = gid >> 6;
    int d4 = gid & 63;
    const float4* GIr = reinterpret_cast<const float4*>(g_GI) + (size_t)n * (K3 / 4);
    const float4* GHr = reinterpret_cast<const float4*>(g_GH) + (size_t)n * (K3 / 4);
    float4 ir  = GIr[d4];
    float4 iz  = GIr[64 + d4];
    float4 in_ = GIr[128 + d4];
    float4 hr  = GHr[d4];
    float4 hz  = GHr[64 + d4];
    float4 hn  = GHr[128 + d4];
    float4 h = reinterpret_cast<const float4*>(memory)[(size_t)n * 64 + d4];
    bool touched = g_cnt[n] > 0.0f;
    float4 o;
    {
        float r = 1.0f / (1.0f + expf(-(ir.x + hr.x)));
        float z = 1.0f / (1.0f + expf(-(iz.x + hz.x)));
        float nn = tanhf(in_.x + r * hn.x);
        o.x = touched ? ((1.0f - z) * nn + z * h.x) : h.x;
    }
    {
        float r = 1.0f / (1.0f + expf(-(ir.y + hr.y)));
        float z = 1.0f / (1.0f + expf(-(iz.y + hz.y)));
        float nn = tanhf(in_.y + r * hn.y);
        o.y = touched ? ((1.0f - z) * nn + z * h.y) : h.y;
    }
    {
        float r = 1.0f / (1.0f + expf(-(ir.z + hr.z)));
        float z = 1.0f / (1.0f + expf(-(iz.z + hz.z)));
        float nn = tanhf(in_.z + r * hn.z);
        o.z = touched ? ((1.0f - z) * nn + z * h.z) : h.z;
    }
    {
        float r = 1.0f / (1.0f + expf(-(ir.w + hr.w)));
        float z = 1.0f / (1.0f + expf(-(iz.w + hz.w)));
        float nn = tanhf(in_.w + r * hn.w);
        o.w = touched ? ((1.0f - z) * nn + z * h.w) : h.w;
    }
    reinterpret_cast<float4*>(out)[gid] = o;
}

// ---------------- host ----------------

extern "C" void kernel_launch(void* const* d_in, const int* in_sizes, int n_in,
                              void* d_out, int out_size) {
    const float* memory   = (const float*)d_in[0];
    const int*   source   = (const int*)d_in[1];
    const int*   target   = (const int*)d_in[2];
    const float* dtv      = (const float*)d_in[3];
    const float* src_w1   = (const float*)d_in[4];
    const float* src_b1   = (const float*)d_in[5];
    const float* src_w2   = (const float*)d_in[6];
    const float* src_b2   = (const float*)d_in[7];
    const float* tar_w1   = (const float*)d_in[8];
    const float* tar_b1   = (const float*)d_in[9];
    const float* tar_w2   = (const float*)d_in[10];
    const float* tar_b2   = (const float*)d_in[11];
    const float* gru_wih  = (const float*)d_in[12];
    const float* gru_whh  = (const float*)d_in[13];
    const float* gru_bih  = (const float*)d_in[14];
    const float* gru_bhh  = (const float*)d_in[15];
    float* out = (float*)d_out;

    static float *pH0 = nullptr, *pH1, *pSums, *pCnt, *pGI, *pGH;
    if (!pH0) {
        cudaGetSymbolAddress((void**)&pH0,   g_H0);
        cudaGetSymbolAddress((void**)&pH1,   g_H1);
        cudaGetSymbolAddress((void**)&pSums, g_sums);
        cudaGetSymbolAddress((void**)&pCnt,  g_cnt);
        cudaGetSymbolAddress((void**)&pGI,   g_GI);
        cudaGetSymbolAddress((void**)&pGH,   g_GH);
    }

    // 1. zero sums + counts, then accumulate counts
    cudaMemsetAsync(pSums, 0, (size_t)NND * DIM * sizeof(float));
    cudaMemsetAsync(pCnt,  0, (size_t)NND * sizeof(float));
    count_kernel<<<BSZ / 256, 256>>>(source, target);

    // 2. hidden = relu(X @ W1^T + b1), X gathered on the fly  [1024 x 256 x 768]
    {
        GemmArgs a0{nullptr, src_w1, src_b1, pH0, nullptr, 0, 1, source, target, memory, dtv};
        GemmArgs a1{nullptr, tar_w1, tar_b1, pH1, nullptr, 0, 1, target, source, memory, dtv};
        dim3 grid(DIM / BN, BSZ / BM, 2);
        mma_gemm_kernel<<<grid, 128>>>(a0, a1, DIM, K3, 1);
    }

    // 3. msg = hidden @ W2^T + b2, fused scatter-add into g_sums
    {
        GemmArgs a0{pH0, src_w2, src_b2, nullptr, source, 0, 0, nullptr, nullptr, nullptr, nullptr};
        GemmArgs a1{pH1, tar_w2, tar_b2, nullptr, target, 0, 0, nullptr, nullptr, nullptr, nullptr};
        dim3 grid(DIM / BN, BSZ / BM, 2);
        mma_gemm_kernel<<<grid, 128>>>(a0, a1, DIM, DIM, 2);
    }

    // 4. GI = (sums/max(cnt,1)) @ wih^T + bih ; GH = memory @ whh^T + bhh
    {
        GemmArgs a0{pSums, gru_wih, gru_bih, pGI, nullptr, 1, 0, nullptr, nullptr, nullptr, nullptr};
        GemmArgs a1{memory, gru_whh, gru_bhh, pGH, nullptr, 0, 0, nullptr, nullptr, nullptr, nullptr};
        dim3 grid(K3 / BN, NND / BM, 2);
        mma_gemm_kernel<<<grid, 128>>>(a0, a1, K3, DIM, 0);
    }

    // 5. GRU elementwise + touched mask
    gru_kernel<<<(NND * DIM / 4) / 256, 256>>>(memory, out);
}

// round 17
// speedup vs baseline: 1.3759x; 1.3759x over previous
#include <cuda_runtime.h>
#include <cstdint>
#include <math.h>

#define BSZ 1024      // batch (edge events)
#define NND 1024      // nodes
#define DIM 256       // feature dim
#define K3  768       // 3*DIM

// GEMM tiling: 64 (M) x 32 (N) CTA tile, BK=32 stages, 128 threads (2x2 warps)
#define BM 64
#define BN 32
#define BKK 32
#define SSTR 36       // smem row stride (floats): conflict-free + 16B-aligned rows

// ---------------- scratch (device globals; no allocation) ----------------
__device__ __align__(16) float g_H0[BSZ * DIM];
__device__ __align__(16) float g_H1[BSZ * DIM];
__device__ __align__(16) float g_sums[NND * DIM];
__device__ __align__(16) float g_cnt[NND];
__device__ __align__(16) float g_GI[NND * K3];
__device__ __align__(16) float g_GH[NND * K3];

// ---------------- PTX helpers ----------------
__device__ __forceinline__ uint32_t smem_u32(const void* p) {
    uint32_t a;
    asm("{ .reg .u64 t; cvta.to.shared.u64 t, %1; cvt.u32.u64 %0, t; }" : "=r"(a) : "l"(p));
    return a;
}
__device__ __forceinline__ uint32_t f2tf32(float x) {
    uint32_t r;
    asm("cvt.rna.tf32.f32 %0, %1;" : "=r"(r) : "f"(x));
    return r;
}
#define CP16(dst, src) \
    asm volatile("cp.async.cg.shared.global [%0], [%1], 16;" :: "r"(dst), "l"(src))
#define CP_COMMIT() asm volatile("cp.async.commit_group;" ::: "memory")
#define CP_WAIT0()  asm volatile("cp.async.wait_group 0;" ::: "memory")
#define CP_WAIT1()  asm volatile("cp.async.wait_group 1;" ::: "memory")

__device__ __forceinline__ void mma_tf32(float* c, const uint32_t* a, const uint32_t* b) {
    asm volatile(
        "mma.sync.aligned.m16n8k8.row.col.f32.tf32.tf32.f32 "
        "{%0,%1,%2,%3}, {%4,%5,%6,%7}, {%8,%9}, {%0,%1,%2,%3};"
        : "+f"(c[0]), "+f"(c[1]), "+f"(c[2]), "+f"(c[3])
        : "r"(a[0]), "r"(a[1]), "r"(a[2]), "r"(a[3]), "r"(b[0]), "r"(b[1]));
}

// ---------------- counts ----------------
__global__ void count_kernel(const int* __restrict__ src,
                             const int* __restrict__ tgt) {
    int i = blockIdx.x * blockDim.x + threadIdx.x;
    if (i < BSZ) {
        atomicAdd(&g_cnt[src[i]], 1.0f);
        atomicAdd(&g_cnt[tgt[i]], 1.0f);
    }
}

// ---------------- tf32 mma.sync GEMM ----------------
// C[M,N] = A[M,K] @ W[N,K]^T + bias[N]
// mode 0: store, 1: relu+store, 2: atomicAdd into g_sums[sidx[row]*DIM + col]
// divA:   scale output row r by 1/max(g_cnt[bm+r],1) (epilogue agg divide)
// GATHER: A row r = concat[ mem[idxA[r]], mem[idxB[r]], dtv[r, idxA[r]] ]
struct GemmArgs {
    const float* A;
    const float* W;
    const float* bias;
    float* C;
    const int* sidx;
    int divA;
    const int* idxA;
    const int* idxB;
};

template <int GATHER>
__global__ __launch_bounds__(128) void gemm_kernel(GemmArgs a0, GemmArgs a1,
                                                   const float* __restrict__ mem,
                                                   const float* __restrict__ dtv,
                                                   int N, int K, int mode) {
    __shared__ __align__(16) float As[2][BM][SSTR];
    __shared__ __align__(16) float Bs[2][BN][SSTR];

    GemmArgs ga = (blockIdx.z == 0) ? a0 : a1;
    const float* __restrict__ W = ga.W;

    int bm = blockIdx.y * BM;
    int bn = blockIdx.x * BN;
    int tid = threadIdx.x;
    int wid = tid >> 5;
    int lane = tid & 31;
    int gidq = lane >> 2;   // 0..7
    int tig  = lane & 3;    // 0..3
    int wm = wid & 1;       // warp m (2)
    int wn = wid >> 1;      // warp n (2)

    // loader mapping: A tile 64 rows x 8 chunks = 512 chunks -> 4/thread
    //                 B tile 32 rows x 8 chunks = 256 chunks -> 2/thread
    int arow = tid >> 3;    // 0..15 (+16*i)
    int ach  = tid & 7;

    // gather: per-thread node indices for its 4 A-rows, loaded once
    int ia[4], ib[4];
    if (GATHER) {
#pragma unroll
        for (int i = 0; i < 4; i++) {
            ia[i] = __ldg(&ga.idxA[bm + arow + 16 * i]);
            ib[i] = __ldg(&ga.idxB[bm + arow + 16 * i]);
        }
    }

    float acc[2][2][4];
#pragma unroll
    for (int i = 0; i < 2; i++)
#pragma unroll
        for (int j = 0; j < 2; j++)
#pragma unroll
            for (int l = 0; l < 4; l++) acc[i][j][l] = 0.0f;

    int nst = K >> 5;

#define LOAD_STAGE(bufi, kb)                                                         \
    do {                                                                             \
        _Pragma("unroll")                                                            \
        for (int i = 0; i < 4; i++) {                                                \
            int row = arow + 16 * i;                                                 \
            const float* src;                                                        \
            if (!GATHER) {                                                           \
                src = ga.A + (size_t)(bm + row) * K + (kb) + ach * 4;                \
            } else {                                                                 \
                int seg = (kb) >> 8;                                                 \
                int sc  = ((kb) & 255) + ach * 4;                                    \
                if (seg == 0)      src = mem + (size_t)ia[i] * DIM + sc;             \
                else if (seg == 1) src = mem + (size_t)ib[i] * DIM + sc;             \
                else               src = dtv + (((size_t)(bm + row) << 8) +          \
                                                (size_t)ia[i]) * DIM + sc;           \
            }                                                                        \
            CP16(smem_u32(&As[bufi][row][ach * 4]), src);                            \
        }                                                                            \
        _Pragma("unroll")                                                            \
        for (int i = 0; i < 2; i++) {                                                \
            int cid = tid + i * 128;                                                 \
            int brow = cid >> 3;                                                     \
            int bch  = cid & 7;                                                      \
            CP16(smem_u32(&Bs[bufi][brow][bch * 4]),                                 \
                 W + (size_t)(bn + brow) * K + (kb) + bch * 4);                      \
        }                                                                            \
        CP_COMMIT();                                                                 \
    } while (0)
    // note: dtv row offset = (bm+row)*NND*DIM = (bm+row)<<8 * DIM since NND*DIM=DIM<<10;
    // written as ((bm+row)<<8)*DIM *? -- careful: (bm+row)*NND = (bm+row)<<10, then *DIM.
    // Using (((size_t)(bm+row) << 10) + ia[i]) * DIM below instead.

#undef LOAD_STAGE
#define LOAD_STAGE(bufi, kb)                                                         \
    do {                                                                             \
        _Pragma("unroll")                                                            \
        for (int i = 0; i < 4; i++) {                                                \
            int row = arow + 16 * i;                                                 \
            const float* src;                                                        \
            if (!GATHER) {                                                           \
                src = ga.A + (size_t)(bm + row) * K + (kb) + ach * 4;                \
            } else {                                                                 \
                int seg = (kb) >> 8;                                                 \
                int sc  = ((kb) & 255) + ach * 4;                                    \
                if (seg == 0)      src = mem + (size_t)ia[i] * DIM + sc;             \
                else if (seg == 1) src = mem + (size_t)ib[i] * DIM + sc;             \
                else               src = dtv + (((size_t)(bm + row) << 10) +         \
                                                (size_t)ia[i]) * DIM + sc;           \
            }                                                                        \
            CP16(smem_u32(&As[bufi][row][ach * 4]), src);                            \
        }                                                                            \
        _Pragma("unroll")                                                            \
        for (int i = 0; i < 2; i++) {                                                \
            int cid = tid + i * 128;                                                 \
            int brow = cid >> 3;                                                     \
            int bch  = cid & 7;                                                      \
            CP16(smem_u32(&Bs[bufi][brow][bch * 4]),                                 \
                 W + (size_t)(bn + brow) * K + (kb) + bch * 4);                      \
        }                                                                            \
        CP_COMMIT();                                                                 \
    } while (0)

    LOAD_STAGE(0, 0);

    int buf = 0;
    for (int s = 0; s < nst; s++) {
        if (s + 1 < nst) {
            int nb = buf ^ 1;
            LOAD_STAGE(nb, (s + 1) * BKK);
            CP_WAIT1();
        } else {
            CP_WAIT0();
        }
        __syncthreads();

#pragma unroll
        for (int ks = 0; ks < 4; ks++) {
            int k0 = ks * 8;
            uint32_t afr[2][4];
#pragma unroll
            for (int ma = 0; ma < 2; ma++) {
                int r = wm * 32 + ma * 16 + gidq;
                afr[ma][0] = f2tf32(As[buf][r][k0 + tig]);
                afr[ma][1] = f2tf32(As[buf][r + 8][k0 + tig]);
                afr[ma][2] = f2tf32(As[buf][r][k0 + tig + 4]);
                afr[ma][3] = f2tf32(As[buf][r + 8][k0 + tig + 4]);
            }
            uint32_t bfr[2][2];
#pragma unroll
            for (int na = 0; na < 2; na++) {
                int c = wn * 16 + na * 8 + gidq;
                bfr[na][0] = f2tf32(Bs[buf][c][k0 + tig]);
                bfr[na][1] = f2tf32(Bs[buf][c][k0 + tig + 4]);
            }
#pragma unroll
            for (int ma = 0; ma < 2; ma++)
#pragma unroll
                for (int na = 0; na < 2; na++)
                    mma_tf32(acc[ma][na], afr[ma], bfr[na]);
        }
        __syncthreads();
        buf ^= 1;
    }

    // ---- epilogue: bias / relu / divA-scale / scatter ----
#pragma unroll
    for (int ma = 0; ma < 2; ma++) {
        int rl0 = wm * 32 + ma * 16 + gidq;
        int rl1 = rl0 + 8;
        float s0 = 1.0f, s1 = 1.0f;
        if (ga.divA) {
            s0 = 1.0f / fmaxf(g_cnt[bm + rl0], 1.0f);
            s1 = 1.0f / fmaxf(g_cnt[bm + rl1], 1.0f);
        }
#pragma unroll
        for (int na = 0; na < 2; na++) {
            int cl = wn * 16 + na * 8 + tig * 2;
            int cg = bn + cl;
            float b0v = ga.bias[cg];
            float b1v = ga.bias[cg + 1];
            float v00 = acc[ma][na][0] * s0 + b0v;
            float v01 = acc[ma][na][1] * s0 + b1v;
            float v10 = acc[ma][na][2] * s1 + b0v;
            float v11 = acc[ma][na][3] * s1 + b1v;
            if (mode == 1) {
                v00 = fmaxf(v00, 0.0f); v01 = fmaxf(v01, 0.0f);
                v10 = fmaxf(v10, 0.0f); v11 = fmaxf(v11, 0.0f);
            }
            if (mode == 2) {
                int n0 = ga.sidx[bm + rl0];
                int n1 = ga.sidx[bm + rl1];
                atomicAdd(&g_sums[(size_t)n0 * DIM + cg],     v00);
                atomicAdd(&g_sums[(size_t)n0 * DIM + cg + 1], v01);
                atomicAdd(&g_sums[(size_t)n1 * DIM + cg],     v10);
                atomicAdd(&g_sums[(size_t)n1 * DIM + cg + 1], v11);
            } else {
                *reinterpret_cast<float2*>(ga.C + (size_t)(bm + rl0) * N + cg) =
                    make_float2(v00, v01);
                *reinterpret_cast<float2*>(ga.C + (size_t)(bm + rl1) * N + cg) =
                    make_float2(v10, v11);
            }
        }
    }
}

// ---------------- GRU elementwise + touched mask ----------------
__global__ void gru_kernel(const float* __restrict__ memory,
                           float* __restrict__ out) {
    int gid = blockIdx.x * blockDim.x + threadIdx.x;
    int n  = gid >> 6;
    int d4 = gid & 63;
    const float4* GIr = reinterpret_cast<const float4*>(g_GI) + (size_t)n * (K3 / 4);
    const float4* GHr = reinterpret_cast<const float4*>(g_GH) + (size_t)n * (K3 / 4);
    float4 ir  = GIr[d4];
    float4 iz  = GIr[64 + d4];
    float4 in_ = GIr[128 + d4];
    float4 hr  = GHr[d4];
    float4 hz  = GHr[64 + d4];
    float4 hn  = GHr[128 + d4];
    float4 h = reinterpret_cast<const float4*>(memory)[(size_t)n * 64 + d4];
    bool touched = g_cnt[n] > 0.0f;
    float4 o;
    {
        float r = 1.0f / (1.0f + expf(-(ir.x + hr.x)));
        float z = 1.0f / (1.0f + expf(-(iz.x + hz.x)));
        float nn = tanhf(in_.x + r * hn.x);
        o.x = touched ? ((1.0f - z) * nn + z * h.x) : h.x;
    }
    {
        float r = 1.0f / (1.0f + expf(-(ir.y + hr.y)));
        float z = 1.0f / (1.0f + expf(-(iz.y + hz.y)));
        float nn = tanhf(in_.y + r * hn.y);
        o.y = touched ? ((1.0f - z) * nn + z * h.y) : h.y;
    }
    {
        float r = 1.0f / (1.0f + expf(-(ir.z + hr.z)));
        float z = 1.0f / (1.0f + expf(-(iz.z + hz.z)));
        float nn = tanhf(in_.z + r * hn.z);
        o.z = touched ? ((1.0f - z) * nn + z * h.z) : h.z;
    }
    {
        float r = 1.0f / (1.0f + expf(-(ir.w + hr.w)));
        float z = 1.0f / (1.0f + expf(-(iz.w + hz.w)));
        float nn = tanhf(in_.w + r * hn.w);
        o.w = touched ? ((1.0f - z) * nn + z * h.w) : h.w;
    }
    reinterpret_cast<float4*>(out)[gid] = o;
}

// ---------------- host ----------------

extern "C" void kernel_launch(void* const* d_in, const int* in_sizes, int n_in,
                              void* d_out, int out_size) {
    const float* memory   = (const float*)d_in[0];
    const int*   source   = (const int*)d_in[1];
    const int*   target   = (const int*)d_in[2];
    const float* dtv      = (const float*)d_in[3];
    const float* src_w1   = (const float*)d_in[4];
    const float* src_b1   = (const float*)d_in[5];
    const float* src_w2   = (const float*)d_in[6];
    const float* src_b2   = (const float*)d_in[7];
    const float* tar_w1   = (const float*)d_in[8];
    const float* tar_b1   = (const float*)d_in[9];
    const float* tar_w2   = (const float*)d_in[10];
    const float* tar_b2   = (const float*)d_in[11];
    const float* gru_wih  = (const float*)d_in[12];
    const float* gru_whh  = (const float*)d_in[13];
    const float* gru_bih  = (const float*)d_in[14];
    const float* gru_bhh  = (const float*)d_in[15];
    float* out = (float*)d_out;

    static float *pH0 = nullptr, *pH1, *pSums, *pCnt, *pGI, *pGH;
    if (!pH0) {
        cudaGetSymbolAddress((void**)&pH0,   g_H0);
        cudaGetSymbolAddress((void**)&pH1,   g_H1);
        cudaGetSymbolAddress((void**)&pSums, g_sums);
        cudaGetSymbolAddress((void**)&pCnt,  g_cnt);
        cudaGetSymbolAddress((void**)&pGI,   g_GI);
        cudaGetSymbolAddress((void**)&pGH,   g_GH);
    }

    // 1. zero sums + counts, accumulate counts
    cudaMemsetAsync(pSums, 0, (size_t)NND * DIM * sizeof(float));
    cudaMemsetAsync(pCnt,  0, (size_t)NND * sizeof(float));
    count_kernel<<<BSZ / 256, 256>>>(source, target);

    // 2. hidden = relu(X @ W1^T + b1), X gathered on the fly  [1024 x 256 x 768]
    {
        GemmArgs a0{nullptr, src_w1, src_b1, pH0, nullptr, 0, source, target};
        GemmArgs a1{nullptr, tar_w1, tar_b1, pH1, nullptr, 0, target, source};
        dim3 grid(DIM / BN, BSZ / BM, 2);   // 8 x 16 x 2 = 256
        gemm_kernel<1><<<grid, 128>>>(a0, a1, memory, dtv, DIM, K3, 1);
    }

    // 3. msg = hidden @ W2^T + b2, fused scatter-add into g_sums
    {
        GemmArgs a0{pH0, src_w2, src_b2, nullptr, source, 0, nullptr, nullptr};
        GemmArgs a1{pH1, tar_w2, tar_b2, nullptr, target, 0, nullptr, nullptr};
        dim3 grid(DIM / BN, BSZ / BM, 2);   // 256
        gemm_kernel<0><<<grid, 128>>>(a0, a1, nullptr, nullptr, DIM, DIM, 2);
    }

    // 4. GI = (sums/max(cnt,1)) @ wih^T + bih ; GH = memory @ whh^T + bhh
    {
        GemmArgs a0{pSums, gru_wih, gru_bih, pGI, nullptr, 1, nullptr, nullptr};
        GemmArgs a1{memory, gru_whh, gru_bhh, pGH, nullptr, 0, nullptr, nullptr};
        dim3 grid(K3 / BN, NND / BM, 2);    // 24 x 16 x 2 = 768
        gemm_kernel<0><<<grid, 128>>>(a0, a1, nullptr, nullptr, K3, DIM, 0);
    }

    // 5. GRU elementwise + touched mask
    gru_kernel<<<(NND * DIM / 4) / 256, 256>>>(memory, out);
}